// round 1
// baseline (speedup 1.0000x reference)
#include <cuda_runtime.h>

#define NTOK   2744
#define BATCH  4
#define CMID   256
#define CIN    1024
#define COUT   1024
#define NHEADS 4
#define DHEAD  64
#define WDIM   14

// ---------------- scratch (static device memory; no allocations) ----------------
__device__ float g_y1 [BATCH*CMID*NTOK];
__device__ float g_q  [BATCH*CMID*NTOK];
__device__ float g_k  [BATCH*CMID*NTOK];
__device__ float g_v  [BATCH*CMID*NTOK];
__device__ float g_rel[NHEADS*DHEAD*NTOK];
__device__ float g_S  [(size_t)BATCH*NHEADS*NTOK*NTOK];   // ~482 MB
__device__ float g_ao [BATCH*CMID*NTOK];
__device__ float g_y3 [BATCH*COUT*NTOK];
__device__ float g_mean[1024];
__device__ float g_istd[1024];

// ---------------- rel position tensor: rel[h*64+d][n] ----------------
__global__ void build_rel_kernel(const float* __restrict__ rh,
                                 const float* __restrict__ rw,
                                 const float* __restrict__ rd) {
    int idx = blockIdx.x * 256 + threadIdx.x;          // < 4*64*2744
    int n  = idx % NTOK;
    int hd = idx / NTOK;
    int w  = n / (WDIM*WDIM);
    int hh = (n / WDIM) % WDIM;
    int dd = n % WDIM;
    g_rel[idx] = rh[(hd*WDIM + hh)*WDIM + dd]
               + rw[(hd*WDIM + w )*WDIM + dd]
               + rd[(hd*WDIM + w )*WDIM + hh];
}

// ---------------- generic NN GEMM: C[M,N] = A[M,K] @ B[K,N] (+bias per row) ----------------
// A row-major (shared across batch), B/C batched via strides, grid.z = batch.
__global__ __launch_bounds__(256) void gemm_nn(
    const float* __restrict__ A, const float* __restrict__ B, float* __restrict__ C,
    int M, int N, int K, long strideB, long strideC, const float* __restrict__ bias)
{
    __shared__ float As[8][132];
    __shared__ float Bs[8][132];
    B += (long)blockIdx.z * strideB;
    C += (long)blockIdx.z * strideC;
    const int bm = blockIdx.y * 128, bn = blockIdx.x * 128;
    const int tid = threadIdx.x;
    const int tx = tid & 15, ty = tid >> 4;

    const int a_row = tid >> 1;             // 0..127
    const int a_k4  = (tid & 1) * 4;        // 0 or 4
    const int b_k   = tid >> 5;             // 0..7
    const int b_n4  = (tid & 31) * 4;       // 0..124

    float acc[8][8] = {};

    for (int k0 = 0; k0 < K; k0 += 8) {
        float4 av = make_float4(0.f,0.f,0.f,0.f);
        int gm = bm + a_row;
        if (gm < M) av = *(const float4*)(A + (long)gm*K + k0 + a_k4);
        As[a_k4+0][a_row] = av.x; As[a_k4+1][a_row] = av.y;
        As[a_k4+2][a_row] = av.z; As[a_k4+3][a_row] = av.w;

        float4 bv = make_float4(0.f,0.f,0.f,0.f);
        int gn = bn + b_n4;
        if (gn < N) bv = *(const float4*)(B + (long)(k0 + b_k)*N + gn);
        *(float4*)&Bs[b_k][b_n4] = bv;
        __syncthreads();

        #pragma unroll
        for (int k = 0; k < 8; k++) {
            float4 a0 = *(float4*)&As[k][ty*8];
            float4 a1 = *(float4*)&As[k][ty*8+4];
            float4 b0 = *(float4*)&Bs[k][tx*8];
            float4 b1 = *(float4*)&Bs[k][tx*8+4];
            float a[8] = {a0.x,a0.y,a0.z,a0.w,a1.x,a1.y,a1.z,a1.w};
            float b[8] = {b0.x,b0.y,b0.z,b0.w,b1.x,b1.y,b1.z,b1.w};
            #pragma unroll
            for (int i = 0; i < 8; i++)
                #pragma unroll
                for (int j = 0; j < 8; j++)
                    acc[i][j] = fmaf(a[i], b[j], acc[i][j]);
        }
        __syncthreads();
    }
    #pragma unroll
    for (int i = 0; i < 8; i++) {
        int gm = bm + ty*8 + i;
        if (gm >= M) continue;
        float bi = bias ? bias[gm] : 0.f;
        #pragma unroll
        for (int j = 0; j < 8; j++) {
            int gn = bn + tx*8 + j;
            if (gn < N) C[(long)gm*N + gn] = acc[i][j] + bi;
        }
    }
}

// ---------------- S = [q;rel]^T [k;q]   (TN GEMM, K=128) ----------------
__global__ __launch_bounds__(256) void gemm_tn_s() {
    const int z = blockIdx.z, b = z >> 2, h = z & 3;
    const float* A0 = g_q  + (size_t)(b*CMID + h*DHEAD)*NTOK;  // rows: n-side (q)
    const float* A1 = g_rel + (size_t)(h*DHEAD)*NTOK;          // rows: n-side (rel)
    const float* B0 = g_k  + (size_t)(b*CMID + h*DHEAD)*NTOK;  // cols: m-side (k)
    const float* B1 = A0;                                      // cols: m-side (q)
    float* C = g_S + (size_t)z*NTOK*NTOK;

    __shared__ float As[8][132];
    __shared__ float Bs[8][132];
    const int tid = threadIdx.x;
    const int bm = blockIdx.y * 128, bn = blockIdx.x * 128;
    const int tx = tid & 15, ty = tid >> 4;
    const int lk  = tid >> 5;
    const int lc4 = (tid & 31) * 4;

    float acc[8][8] = {};

    for (int k0 = 0; k0 < 2*DHEAD; k0 += 8) {
        int kk = k0 + lk;
        const float* ar = (kk < DHEAD) ? A0 + (size_t)kk*NTOK : A1 + (size_t)(kk-DHEAD)*NTOK;
        const float* br = (kk < DHEAD) ? B0 + (size_t)kk*NTOK : B1 + (size_t)(kk-DHEAD)*NTOK;
        float4 av = make_float4(0.f,0.f,0.f,0.f);
        float4 bv = make_float4(0.f,0.f,0.f,0.f);
        if (bm + lc4 < NTOK) av = *(const float4*)(ar + bm + lc4);
        if (bn + lc4 < NTOK) bv = *(const float4*)(br + bn + lc4);
        *(float4*)&As[lk][lc4] = av;
        *(float4*)&Bs[lk][lc4] = bv;
        __syncthreads();

        #pragma unroll
        for (int k = 0; k < 8; k++) {
            float4 a0 = *(float4*)&As[k][ty*8];
            float4 a1 = *(float4*)&As[k][ty*8+4];
            float4 b0 = *(float4*)&Bs[k][tx*8];
            float4 b1 = *(float4*)&Bs[k][tx*8+4];
            float a[8] = {a0.x,a0.y,a0.z,a0.w,a1.x,a1.y,a1.z,a1.w};
            float b[8] = {b0.x,b0.y,b0.z,b0.w,b1.x,b1.y,b1.z,b1.w};
            #pragma unroll
            for (int i = 0; i < 8; i++)
                #pragma unroll
                for (int j = 0; j < 8; j++)
                    acc[i][j] = fmaf(a[i], b[j], acc[i][j]);
        }
        __syncthreads();
    }
    #pragma unroll
    for (int i = 0; i < 8; i++) {
        int gm = bm + ty*8 + i;
        if (gm >= NTOK) continue;
        #pragma unroll
        for (int j = 0; j < 8; j++) {
            int gn = bn + tx*8 + j;
            if (gn < NTOK) C[(size_t)gm*NTOK + gn] = acc[i][j];
        }
    }
}

// ---------------- row softmax over m (in-place on g_S) ----------------
__global__ __launch_bounds__(256) void softmax_rows() {
    const size_t row = (size_t)blockIdx.y * NTOK + blockIdx.x;
    float* p = g_S + row * NTOK;
    const int tid = threadIdx.x;
    __shared__ float red[256];

    float vals[11];
    float m = -1e30f;
    #pragma unroll
    for (int i = 0; i < 11; i++) {
        int idx = tid + i*256;
        float v = (idx < NTOK) ? p[idx] : -1e30f;
        vals[i] = v;
        m = fmaxf(m, v);
    }
    red[tid] = m; __syncthreads();
    for (int s = 128; s > 0; s >>= 1) {
        if (tid < s) red[tid] = fmaxf(red[tid], red[tid+s]);
        __syncthreads();
    }
    m = red[0]; __syncthreads();

    float sum = 0.f;
    #pragma unroll
    for (int i = 0; i < 11; i++) {
        int idx = tid + i*256;
        if (idx < NTOK) { float e = __expf(vals[i] - m); vals[i] = e; sum += e; }
    }
    red[tid] = sum; __syncthreads();
    for (int s = 128; s > 0; s >>= 1) {
        if (tid < s) red[tid] += red[tid+s];
        __syncthreads();
    }
    float inv = 1.f / red[0];
    #pragma unroll
    for (int i = 0; i < 11; i++) {
        int idx = tid + i*256;
        if (idx < NTOK) p[idx] = vals[i] * inv;
    }
}

// ---------------- O[d,n] = sum_m V[d,m] * attn[n,m]  (NT GEMM per (b,h)) ----------------
__global__ __launch_bounds__(256) void gemm_av() {
    const int z = blockIdx.z, b = z >> 2, h = z & 3;
    const float* V = g_v + (size_t)(b*CMID + h*DHEAD)*NTOK;   // [64, N] K-contig
    const float* A = g_S + (size_t)z*NTOK*NTOK;               // [n, m]  K-contig
    float* C = g_ao + (size_t)(b*CMID + h*DHEAD)*NTOK;        // [64, N]

    __shared__ float Vs[8][68];
    __shared__ float Bs[8][132];
    const int tid = threadIdx.x;
    const int bn = blockIdx.x * 128;
    const int tx = tid & 15, ty = tid >> 4;    // d0 = ty*4, n0 = tx*8
    const int lr  = tid >> 1;                  // 0..127
    const int lk4 = (tid & 1) * 4;

    float acc[4][8] = {};

    for (int k0 = 0; k0 < NTOK; k0 += 8) {
        if (tid < 128) {   // lr = 0..63 -> d
            float4 vv = *(const float4*)(V + (size_t)lr*NTOK + k0 + lk4);
            Vs[lk4+0][lr] = vv.x; Vs[lk4+1][lr] = vv.y;
            Vs[lk4+2][lr] = vv.z; Vs[lk4+3][lr] = vv.w;
        }
        {
            int n = bn + lr;
            float4 bv = make_float4(0.f,0.f,0.f,0.f);
            if (n < NTOK) bv = *(const float4*)(A + (size_t)n*NTOK + k0 + lk4);
            Bs[lk4+0][lr] = bv.x; Bs[lk4+1][lr] = bv.y;
            Bs[lk4+2][lr] = bv.z; Bs[lk4+3][lr] = bv.w;
        }
        __syncthreads();
        #pragma unroll
        for (int k = 0; k < 8; k++) {
            float4 a0 = *(float4*)&Vs[k][ty*4];
            float4 b0 = *(float4*)&Bs[k][tx*8];
            float4 b1 = *(float4*)&Bs[k][tx*8+4];
            float a[4] = {a0.x,a0.y,a0.z,a0.w};
            float bb[8] = {b0.x,b0.y,b0.z,b0.w,b1.x,b1.y,b1.z,b1.w};
            #pragma unroll
            for (int i = 0; i < 4; i++)
                #pragma unroll
                for (int j = 0; j < 8; j++)
                    acc[i][j] = fmaf(a[i], bb[j], acc[i][j]);
        }
        __syncthreads();
    }
    #pragma unroll
    for (int i = 0; i < 4; i++) {
        int d = ty*4 + i;
        #pragma unroll
        for (int j = 0; j < 8; j++) {
            int n = bn + tx*8 + j;
            if (n < NTOK) C[(size_t)d*NTOK + n] = acc[i][j];
        }
    }
}

// ---------------- BatchNorm (training-mode) stats per channel ----------------
__global__ __launch_bounds__(256) void bn_stats(const float* __restrict__ x, int C,
                                                float* __restrict__ mean, float* __restrict__ istd) {
    const int c = blockIdx.x;
    const int tid = threadIdx.x;
    float s = 0.f, sq = 0.f;
    for (int i = tid; i < BATCH*NTOK; i += 256) {
        int b = i / NTOK, n = i - b*NTOK;
        float v = x[((long)b*C + c)*NTOK + n];
        s += v; sq += v*v;
    }
    __shared__ float r1[256], r2[256];
    r1[tid] = s; r2[tid] = sq; __syncthreads();
    for (int st = 128; st > 0; st >>= 1) {
        if (tid < st) { r1[tid] += r1[tid+st]; r2[tid] += r2[tid+st]; }
        __syncthreads();
    }
    if (tid == 0) {
        const float inv_cnt = 1.f / (BATCH*NTOK);
        float m = r1[0] * inv_cnt;
        float var = r2[0] * inv_cnt - m*m;
        mean[c] = m;
        istd[c] = rsqrtf(var + 1e-5f);
    }
}

__global__ void bn_apply_relu(float* __restrict__ x, int C,
                              const float* __restrict__ mean, const float* __restrict__ istd,
                              const float* __restrict__ g, const float* __restrict__ bp) {
    long idx = (long)blockIdx.x * 256 + threadIdx.x;
    if (idx >= (long)BATCH*C*NTOK) return;
    int c = (int)((idx / NTOK) % C);
    float v = (x[idx] - mean[c]) * istd[c] * g[c] + bp[c];
    x[idx] = fmaxf(v, 0.f);
}

__global__ void bn_res_relu(const float* __restrict__ y, const float* __restrict__ xres,
                            float* __restrict__ out,
                            const float* __restrict__ mean, const float* __restrict__ istd,
                            const float* __restrict__ g, const float* __restrict__ bp) {
    long idx = (long)blockIdx.x * 256 + threadIdx.x;
    if (idx >= (long)BATCH*COUT*NTOK) return;
    int c = (int)((idx / NTOK) % COUT);
    float v = (y[idx] - mean[c]) * istd[c] * g[c] + bp[c] + xres[idx];
    out[idx] = fmaxf(v, 0.f);
}

// ---------------- launch ----------------
extern "C" void kernel_launch(void* const* d_in, const int* in_sizes, int n_in,
                              void* d_out, int out_size) {
    const float* x    = (const float*)d_in[0];
    const float* W1   = (const float*)d_in[1];
    const float* g1   = (const float*)d_in[2];
    const float* b1   = (const float*)d_in[3];
    const float* Wq   = (const float*)d_in[4];
    const float* bq   = (const float*)d_in[5];
    const float* Wk   = (const float*)d_in[6];
    const float* bk   = (const float*)d_in[7];
    const float* Wv   = (const float*)d_in[8];
    const float* bv   = (const float*)d_in[9];
    const float* relh = (const float*)d_in[10];
    const float* relw = (const float*)d_in[11];
    const float* reld = (const float*)d_in[12];
    const float* g2   = (const float*)d_in[13];
    const float* b2   = (const float*)d_in[14];
    const float* W3   = (const float*)d_in[15];
    const float* g3   = (const float*)d_in[16];
    const float* b3   = (const float*)d_in[17];
    float* out = (float*)d_out;

    float *y1, *q, *k, *v, *ao, *y3, *mean, *istd;
    cudaGetSymbolAddress((void**)&y1,  g_y1);
    cudaGetSymbolAddress((void**)&q,   g_q);
    cudaGetSymbolAddress((void**)&k,   g_k);
    cudaGetSymbolAddress((void**)&v,   g_v);
    cudaGetSymbolAddress((void**)&ao,  g_ao);
    cudaGetSymbolAddress((void**)&y3,  g_y3);
    cudaGetSymbolAddress((void**)&mean,g_mean);
    cudaGetSymbolAddress((void**)&istd,g_istd);

    const dim3 blk(256);
    const int NT = (NTOK + 127) / 128;   // 22

    // conv1: [256,1024] @ x_b -> y1
    gemm_nn<<<dim3(NT, 2, BATCH), blk>>>(W1, x, y1, CMID, NTOK, CIN,
                                         (long)CIN*NTOK, (long)CMID*NTOK, nullptr);
    bn_stats<<<CMID, 256>>>(y1, CMID, mean, istd);
    bn_apply_relu<<<(BATCH*CMID*NTOK)/256, 256>>>(y1, CMID, mean, istd, g1, b1);

    // q,k,v projections (with bias)
    gemm_nn<<<dim3(NT, 2, BATCH), blk>>>(Wq, y1, q, CMID, NTOK, CMID,
                                         (long)CMID*NTOK, (long)CMID*NTOK, bq);
    gemm_nn<<<dim3(NT, 2, BATCH), blk>>>(Wk, y1, k, CMID, NTOK, CMID,
                                         (long)CMID*NTOK, (long)CMID*NTOK, bk);
    gemm_nn<<<dim3(NT, 2, BATCH), blk>>>(Wv, y1, v, CMID, NTOK, CMID,
                                         (long)CMID*NTOK, (long)CMID*NTOK, bv);

    // relative position tensor
    build_rel_kernel<<<(NHEADS*DHEAD*NTOK)/256, 256>>>(relh, relw, reld);

    // attention logits + softmax + AV
    gemm_tn_s<<<dim3(NT, NT, BATCH*NHEADS), blk>>>();
    softmax_rows<<<dim3(NTOK, BATCH*NHEADS), blk>>>();
    gemm_av<<<dim3(NT, 1, BATCH*NHEADS), blk>>>();

    // BN2 + ReLU
    bn_stats<<<CMID, 256>>>(ao, CMID, mean, istd);
    bn_apply_relu<<<(BATCH*CMID*NTOK)/256, 256>>>(ao, CMID, mean, istd, g2, b2);

    // conv3: [1024,256] @ ao_b -> y3
    gemm_nn<<<dim3(NT, 8, BATCH), blk>>>(W3, ao, y3, COUT, NTOK, CMID,
                                         (long)CMID*NTOK, (long)COUT*NTOK, nullptr);
    bn_stats<<<COUT, 256>>>(y3, COUT, mean, istd);
    bn_res_relu<<<(BATCH*COUT*NTOK)/256, 256>>>(y3, x, out, mean, istd, g3, b3);
}